// round 15
// baseline (speedup 1.0000x reference)
#include <cuda_runtime.h>
#include <math.h>

// Problem: D [n, 512] fp32 row-major.
//   diag[j]  = sum_i D[i][j]^2
//   out      = 0.001 * sqrt( sum_j (diag[j]-1)^2 )
//
// Fully fused single kernel:
//   - 592 blocks (one wave) stream D at HBM roofline, squared-accumulate.
//   - Block-level shared combine -> 512 partials/block.
//   - RED.ADD.F32 into g_diag[512] (L2 atomics; ~592 adds/addr over 184 LTS
//     slices -> ~1-2us drain, overlapped with tail).
//   - threadfence + ticket elects the last block to finish: residual norm in
//     double, write out, and reset g_diag/g_ticket for the next graph replay.

#define D_COLS 512
#define NB     592           // 148 SMs x 4 CTAs = exactly one wave
#define TPB    256           // 128 threads per row, 2 rows per block-iteration

// Column squared-norm accumulator. Zero at load; reset by elected block.
__device__ float g_diag[D_COLS];
// Ticket counter for last-block election. Zero at load; reset each run.
__device__ unsigned int g_ticket;

__global__ void __launch_bounds__(TPB, 4)
colsq_fused_kernel(const float* __restrict__ D, int n, float* __restrict__ out) {
    const int tid  = threadIdx.x;
    const int c4   = tid & 127;        // which float4 within the 512-col row
    const int rsub = tid >> 7;         // 0 or 1: which of the block's 2 rows
    const float4* __restrict__ Dv = (const float4*)D;

    float a0 = 0.f, a1 = 0.f, a2 = 0.f, a3 = 0.f;

    const int stride = NB * 2;         // rows advanced per grid iteration
    int row = blockIdx.x * 2 + rsub;

    #pragma unroll 8
    for (; row < n; row += stride) {
        float4 v = Dv[(size_t)row * 128 + c4];
        a0 = fmaf(v.x, v.x, a0);
        a1 = fmaf(v.y, v.y, a1);
        a2 = fmaf(v.z, v.z, a2);
        a3 = fmaf(v.w, v.w, a3);
    }

    // Combine the two row-halves of the block in shared memory.
    __shared__ float4 s[TPB];
    s[tid] = make_float4(a0, a1, a2, a3);
    __syncthreads();

    if (tid < 128) {
        float4 lo = s[tid];
        float4 hi = s[tid + 128];
        // Columns [4*tid, 4*tid+3]: add block partial into global accumulator.
        atomicAdd(&g_diag[4 * tid + 0], lo.x + hi.x);
        atomicAdd(&g_diag[4 * tid + 1], lo.y + hi.y);
        atomicAdd(&g_diag[4 * tid + 2], lo.z + hi.z);
        atomicAdd(&g_diag[4 * tid + 3], lo.w + hi.w);
    }

    // Order this block's RED ops before its ticket increment.
    __threadfence();
    __syncthreads();                   // tid 0's ticket happens-after all fences
    __shared__ unsigned int s_last;
    if (tid == 0) {
        unsigned int t = atomicAdd(&g_ticket, 1u);
        s_last = (t == (unsigned int)(NB - 1)) ? 1u : 0u;
    }
    __syncthreads();
    if (!s_last) return;

    // Elected last block: all 592 blocks' atomics are visible in L2.
    // 256 threads, 2 columns each.
    float d0 = __ldcg(&g_diag[tid]);
    float d1 = __ldcg(&g_diag[tid + 256]);
    double r0 = (double)d0 - 1.0;
    double r1 = (double)d1 - 1.0;

    // Reset accumulators for the next graph replay (visible at next launch
    // via stream ordering).
    g_diag[tid]       = 0.f;
    g_diag[tid + 256] = 0.f;

    __shared__ double sh[TPB];
    sh[tid] = r0 * r0 + r1 * r1;
    __syncthreads();
    #pragma unroll
    for (int off = TPB / 2; off > 0; off >>= 1) {
        if (tid < off) sh[tid] += sh[tid + off];
        __syncthreads();
    }

    if (tid == 0) {
        out[0] = (float)(0.001 * sqrt(sh[0]));
        g_ticket = 0u;                 // reset for next replay
    }
}

extern "C" void kernel_launch(void* const* d_in, const int* in_sizes, int n_in,
                              void* d_out, int out_size) {
    const float* D = (const float*)d_in[0];
    const int n = in_sizes[0] / D_COLS;     // rows
    float* out = (float*)d_out;

    colsq_fused_kernel<<<NB, TPB>>>(D, n, out);
}

// round 16
// speedup vs baseline: 1.1696x; 1.1696x over previous
#include <cuda_runtime.h>
#include <math.h>

// Problem: D [n, 512] fp32 row-major.
//   diag[j]  = sum_i D[i][j]^2
//   out      = 0.001 * sqrt( sum_j (diag[j]-1)^2 )
//
// Fully fused single kernel:
//   - 592 blocks (one wave) stream D at HBM roofline, squared-accumulate.
//   - Block-level shared combine -> 512 partials/block.
//   - RED.ADD.F32 into a PADDED accumulator: one column per 256B line
//     (128KB footprint) so the 512 atomic targets spread across all LTS
//     slices instead of 16 lines (R15's 22us drain -> ~1-2us).
//   - threadfence + ticket elects the last block: residual norm in double,
//     write out, reset accumulator + ticket for the next graph replay.

#define D_COLS 512
#define NB     592           // 148 SMs x 4 CTAs = exactly one wave
#define TPB    256           // 128 threads per row, 2 rows per block-iteration
#define PAD    64            // floats between columns: 256B -> distinct L2 lines

// Padded column accumulator: 512 cols x 64-float stride = 128KB static.
__device__ float g_diag_pad[D_COLS * PAD];
// Ticket counter for last-block election. Zero at load; reset each run.
__device__ unsigned int g_ticket;

__global__ void __launch_bounds__(TPB, 4)
colsq_fused_kernel(const float* __restrict__ D, int n, float* __restrict__ out) {
    const int tid  = threadIdx.x;
    const int c4   = tid & 127;        // which float4 within the 512-col row
    const int rsub = tid >> 7;         // 0 or 1: which of the block's 2 rows
    const float4* __restrict__ Dv = (const float4*)D;

    float a0 = 0.f, a1 = 0.f, a2 = 0.f, a3 = 0.f;

    const int stride = NB * 2;         // rows advanced per grid iteration
    int row = blockIdx.x * 2 + rsub;

    #pragma unroll 8
    for (; row < n; row += stride) {
        float4 v = Dv[(size_t)row * 128 + c4];
        a0 = fmaf(v.x, v.x, a0);
        a1 = fmaf(v.y, v.y, a1);
        a2 = fmaf(v.z, v.z, a2);
        a3 = fmaf(v.w, v.w, a3);
    }

    // Combine the two row-halves of the block in shared memory.
    __shared__ float4 s[TPB];
    s[tid] = make_float4(a0, a1, a2, a3);
    __syncthreads();

    if (tid < 128) {
        float4 lo = s[tid];
        float4 hi = s[tid + 128];
        // Columns [4*tid, 4*tid+3], each on its own 256B-spaced address.
        atomicAdd(&g_diag_pad[(4 * tid + 0) * PAD], lo.x + hi.x);
        atomicAdd(&g_diag_pad[(4 * tid + 1) * PAD], lo.y + hi.y);
        atomicAdd(&g_diag_pad[(4 * tid + 2) * PAD], lo.z + hi.z);
        atomicAdd(&g_diag_pad[(4 * tid + 3) * PAD], lo.w + hi.w);
    }

    // Order this block's RED ops before its ticket increment.
    __threadfence();
    __syncthreads();                   // tid 0's ticket happens-after all fences
    __shared__ unsigned int s_last;
    if (tid == 0) {
        unsigned int t = atomicAdd(&g_ticket, 1u);
        s_last = (t == (unsigned int)(NB - 1)) ? 1u : 0u;
    }
    __syncthreads();
    if (!s_last) return;

    // Elected last block: all 592 blocks' atomics are visible in L2.
    // 256 threads, 2 columns each (stride-PAD reads, L2-resident).
    float d0 = __ldcg(&g_diag_pad[tid * PAD]);
    float d1 = __ldcg(&g_diag_pad[(tid + 256) * PAD]);
    double r0 = (double)d0 - 1.0;
    double r1 = (double)d1 - 1.0;

    // Reset accumulators for the next graph replay (visible at next launch
    // via stream ordering).
    g_diag_pad[tid * PAD]         = 0.f;
    g_diag_pad[(tid + 256) * PAD] = 0.f;

    __shared__ double sh[TPB];
    sh[tid] = r0 * r0 + r1 * r1;
    __syncthreads();
    #pragma unroll
    for (int off = TPB / 2; off > 0; off >>= 1) {
        if (tid < off) sh[tid] += sh[tid + off];
        __syncthreads();
    }

    if (tid == 0) {
        out[0] = (float)(0.001 * sqrt(sh[0]));
        g_ticket = 0u;                 // reset for next replay
    }
}

extern "C" void kernel_launch(void* const* d_in, const int* in_sizes, int n_in,
                              void* d_out, int out_size) {
    const float* D = (const float*)d_in[0];
    const int n = in_sizes[0] / D_COLS;     // rows
    float* out = (float*)d_out;

    colsq_fused_kernel<<<NB, TPB>>>(D, n, out);
}